// round 1
// baseline (speedup 1.0000x reference)
#include <cuda_runtime.h>

#define NN 2048
#define TT 2048
#define NBLK 128          // persistent blocks, 1 per SM (<=148 SMs -> all co-resident)
#define NC 16             // output columns per block (128*16 = 2048)
#define NTHR 256
#define RPT 8             // rows per thread (2048/256)
#define WS_STRIDE 20      // padded floats per smem row (conflict-free LDS.128)

#define SMEM_FLOATS (NN * WS_STRIDE + 8 * NC)
#define SMEM_BYTES  (SMEM_FLOATS * 4)

// Scratch (device globals: no allocation allowed)
__device__ float g_sbuf[2][NN];
__device__ float g_sfbuf[2][NN];
__device__ float g_shist[(size_t)TT * NN];   // s_new history for deferred readout
__device__ volatile unsigned g_flags[NBLK];  // per-block epoch flags (grid barrier)

__global__ void init_kernel() {
    int i = blockIdx.x * blockDim.x + threadIdx.x;
    if (i < NN) { g_sbuf[0][i] = 0.0f; g_sfbuf[0][i] = 0.0f; }
    if (i < NBLK) g_flags[i] = 0u;
}

__global__ void __launch_bounds__(NTHR, 1) nlif_kernel(
    const float* __restrict__ x_in,   // (T,2)
    const float* __restrict__ W_syn,  // (N,N)
    const float* __restrict__ W_fast, // (N,N)
    const float* __restrict__ W_in,   // (2,N)
    const float* __restrict__ I_o,    // (N,)
    float* __restrict__ spikes_out,   // (T,N)
    float* __restrict__ vs_out)       // (T,N)
{
    extern __shared__ float sm[];
    float* ws      = sm;                    // [NN * WS_STRIDE] W_syn col slice
    float* partial = sm + NN * WS_STRIDE;   // [8 warps][NC]

    const int tid  = threadIdx.x;
    const int b    = blockIdx.x;
    const int cb   = b * NC;                // first global column owned
    const int lane = tid & 31;
    const int warp = tid >> 5;

    // ---- Load W_fast slice into registers: wf[k][q] = W_fast[tid+256k][cb+4q..+3]
    float4 wf[RPT][4];
#pragma unroll
    for (int k = 0; k < RPT; k++) {
        int r = tid + k * NTHR;
        const float4* p = (const float4*)(W_fast + (size_t)r * NN + cb);
#pragma unroll
        for (int q = 0; q < 4; q++) wf[k][q] = p[q];
    }

    // ---- Load W_syn slice into smem (padded), zero the diagonal element
#pragma unroll
    for (int k = 0; k < RPT; k++) {
        int r = tid + k * NTHR;
        const float4* p = (const float4*)(W_syn + (size_t)r * NN + cb);
        float4* dst = (float4*)(ws + r * WS_STRIDE);
#pragma unroll
        for (int q = 0; q < 4; q++) dst[q] = p[q];
        if (r >= cb && r < cb + NC) ws[r * WS_STRIDE + (r - cb)] = 0.0f;
    }

    // ---- Per-neuron state kept in registers of threads 0..NC-1
    float v_st = 0.0f, s_st = 0.0f;
    float win0 = 0.0f, win1 = 0.0f, io = 0.0f;
    if (tid < NC) {
        int j = cb + tid;
        win0 = __ldg(W_in + j);
        win1 = __ldg(W_in + NN + j);
        io   = __ldg(I_o + j);
    }
    __syncthreads();

    for (int t = 0; t < TT; t++) {
        // ---- grid barrier: wait until every block has published step t
        if (t > 0) {
            if (tid < 32) {
                unsigned need = (unsigned)t;
                while (g_flags[lane] < need || g_flags[lane + 32] < need ||
                       g_flags[lane + 64] < need || g_flags[lane + 96] < need) { }
            }
            __syncthreads();
        }

        const float* sb  = &g_sbuf[t & 1][0];
        const float* sfb = &g_sfbuf[t & 1][0];

        // ---- load this thread's 8 s / s_fast values (bypass L1: cross-SM data)
        float sv[RPT], fv[RPT];
#pragma unroll
        for (int k = 0; k < RPT; k++) {
            int r = tid + k * NTHR;
            sv[k] = __ldcg(sb + r);
            fv[k] = __ldcg(sfb + r);
        }

        // ---- partial mat-vec: acc[c] = sum_k s*Wsyn + sfast*Wfast
        float4 a0 = make_float4(0.f,0.f,0.f,0.f);
        float4 a1 = a0, a2 = a0, a3 = a0;
#pragma unroll
        for (int k = 0; k < RPT; k++) {
            const float4* wr = (const float4*)(ws + (tid + k * NTHR) * WS_STRIDE);
            float4 w0 = wr[0], w1 = wr[1], w2 = wr[2], w3 = wr[3];
            float s = sv[k], f = fv[k];
            a0.x += s*w0.x + f*wf[k][0].x;  a0.y += s*w0.y + f*wf[k][0].y;
            a0.z += s*w0.z + f*wf[k][0].z;  a0.w += s*w0.w + f*wf[k][0].w;
            a1.x += s*w1.x + f*wf[k][1].x;  a1.y += s*w1.y + f*wf[k][1].y;
            a1.z += s*w1.z + f*wf[k][1].z;  a1.w += s*w1.w + f*wf[k][1].w;
            a2.x += s*w2.x + f*wf[k][2].x;  a2.y += s*w2.y + f*wf[k][2].y;
            a2.z += s*w2.z + f*wf[k][2].z;  a2.w += s*w2.w + f*wf[k][2].w;
            a3.x += s*w3.x + f*wf[k][3].x;  a3.y += s*w3.y + f*wf[k][3].y;
            a3.z += s*w3.z + f*wf[k][3].z;  a3.w += s*w3.w + f*wf[k][3].w;
        }

        // ---- intra-warp butterfly reduce all 16 column partials
        float v16[NC] = { a0.x,a0.y,a0.z,a0.w, a1.x,a1.y,a1.z,a1.w,
                          a2.x,a2.y,a2.z,a2.w, a3.x,a3.y,a3.z,a3.w };
#pragma unroll
        for (int c = 0; c < NC; c++) {
            float x = v16[c];
            x += __shfl_xor_sync(0xffffffffu, x, 16);
            x += __shfl_xor_sync(0xffffffffu, x, 8);
            x += __shfl_xor_sync(0xffffffffu, x, 4);
            x += __shfl_xor_sync(0xffffffffu, x, 2);
            x += __shfl_xor_sync(0xffffffffu, x, 1);
            v16[c] = x;
        }
        if (lane == 0) {
#pragma unroll
            for (int c = 0; c < NC; c++) partial[warp * NC + c] = v16[c];
        }
        __syncthreads();

        // ---- state update for the 16 owned neurons
        if (tid < NC) {
            float Irec = 0.0f;
#pragma unroll
            for (int w = 0; w < 8; w++) Irec += partial[w * NC + tid];
            float x0 = __ldg(x_in + 2 * t);
            float x1 = __ldg(x_in + 2 * t + 1);
            float Itot = Irec + x0 * win0 + x1 * win1 + io;
            float dv = __fdiv_rn(Itot - v_st, 10.0f);      // /TAU_M
            float vn = v_st + dv;
            float g   = fminf(fmaxf(vn, -1.0f), 1.0f);
            float dvc = fminf(fmaxf(dv, -1.0f), 1.0f);
            float gd  = g * dvc;
            float s_new  = s_st + __fdiv_rn(gd - s_st, 10.0f);  // /TAU_S
            float sf_new = gd;
            float sp  = (vn >= 1.0f)  ? 1.0f : 0.0f;
            float sng = (vn <= -1.0f) ? 1.0f : 0.0f;
            float v_new = (sp + 1.0f - sng) * vn;   // matches reference "not_spiked" algebra

            int j = cb + tid;
            size_t off = (size_t)t * NN + j;
            spikes_out[off] = sp;
            vs_out[off]     = v_new;
            g_shist[off]    = s_new;
            int np = (t + 1) & 1;
            __stcg(&g_sbuf[np][j],  s_new);
            __stcg(&g_sfbuf[np][j], sf_new);
            v_st = v_new; s_st = s_new;
        }

        // ---- publish: make writes GPU-visible, then raise this block's flag
        __threadfence();
        __syncthreads();
        if (tid == 0) g_flags[b] = (unsigned)(t + 1);
    }
}

// Deferred readout: readouts[t] = O @ s_hist[t]
__global__ void readout_kernel(const float* __restrict__ O, float* __restrict__ readouts) {
    int t = blockIdx.x;
    int tid = threadIdx.x;
    const float* sh = g_shist + (size_t)t * NN;
    float a0 = 0.0f, a1 = 0.0f;
    for (int j = tid; j < NN; j += blockDim.x) {
        float s = sh[j];
        a0 += O[j] * s;
        a1 += O[NN + j] * s;
    }
#pragma unroll
    for (int o = 16; o > 0; o >>= 1) {
        a0 += __shfl_xor_sync(0xffffffffu, a0, o);
        a1 += __shfl_xor_sync(0xffffffffu, a1, o);
    }
    __shared__ float r0[8], r1[8];
    if ((tid & 31) == 0) { r0[tid >> 5] = a0; r1[tid >> 5] = a1; }
    __syncthreads();
    if (tid == 0) {
        float x = 0.0f, y = 0.0f;
#pragma unroll
        for (int w = 0; w < 8; w++) { x += r0[w]; y += r1[w]; }
        readouts[2 * t]     = x;
        readouts[2 * t + 1] = y;
    }
}

extern "C" void kernel_launch(void* const* d_in, const int* in_sizes, int n_in,
                              void* d_out, int out_size) {
    const float* x_in   = (const float*)d_in[0];
    const float* W_syn  = (const float*)d_in[1];
    const float* W_fast = (const float*)d_in[2];
    const float* W_in   = (const float*)d_in[3];
    const float* I_o    = (const float*)d_in[4];
    const float* O      = (const float*)d_in[5];

    float* out      = (float*)d_out;
    float* spikes   = out;                                  // (T,N)
    float* readouts = out + (size_t)TT * NN;                // (T,2)
    float* vs       = out + (size_t)TT * NN + 2 * (size_t)TT; // (T,N)

    cudaFuncSetAttribute(nlif_kernel, cudaFuncAttributeMaxDynamicSharedMemorySize, SMEM_BYTES);

    init_kernel<<<(NN + 255) / 256, 256>>>();
    nlif_kernel<<<NBLK, NTHR, SMEM_BYTES>>>(x_in, W_syn, W_fast, W_in, I_o, spikes, vs);
    readout_kernel<<<TT, 256>>>(O, readouts);
}

// round 2
// speedup vs baseline: 1.1811x; 1.1811x over previous
#include <cuda_runtime.h>

#define NN 2048
#define TT 2048
#define NBLK 128          // persistent blocks, 1 per SM (<=148 SMs -> all co-resident)
#define NC 16             // output columns per block (128*16 = 2048)
#define NTHR 256
#define RPT 8             // rows per thread (2048/256)
#define WS_STRIDE 20      // padded floats per smem row (conflict-free LDS.128)

#define SMEM_FLOATS (NN * WS_STRIDE + 8 * NC)
#define SMEM_BYTES  (SMEM_FLOATS * 4)

// Scratch (device globals: no allocation allowed)
__device__ float g_sbuf[2][NN];
__device__ float g_sfbuf[2][NN];
__device__ float g_shist[(size_t)TT * NN];   // s_new history for deferred readout
__device__ volatile unsigned g_flags[NBLK];  // per-block epoch flags (grid barrier)

__global__ void init_kernel() {
    int i = blockIdx.x * blockDim.x + threadIdx.x;
    if (i < NN) { g_sbuf[0][i] = 0.0f; g_sfbuf[0][i] = 0.0f; }
    if (i < NBLK) g_flags[i] = 0u;
}

__global__ void __launch_bounds__(NTHR, 1) nlif_kernel(
    const float* __restrict__ x_in,   // (T,2)
    const float* __restrict__ W_syn,  // (N,N)
    const float* __restrict__ W_fast, // (N,N)
    const float* __restrict__ W_in,   // (2,N)
    const float* __restrict__ I_o,    // (N,)
    float* __restrict__ spikes_out,   // (T,N)
    float* __restrict__ vs_out)       // (T,N)
{
    extern __shared__ float sm[];
    float* ws      = sm;                    // [NN * WS_STRIDE] W_syn col slice
    float* partial = sm + NN * WS_STRIDE;   // [8 warps][NC]

    const int tid  = threadIdx.x;
    const int b    = blockIdx.x;
    const int cb   = b * NC;                // first global column owned
    const int lane = tid & 31;
    const int warp = tid >> 5;

    // ---- Load W_fast slice into registers: wf[k][q] = W_fast[tid+256k][cb+4q..+3]
    float4 wf[RPT][4];
#pragma unroll
    for (int k = 0; k < RPT; k++) {
        int r = tid + k * NTHR;
        const float4* p = (const float4*)(W_fast + (size_t)r * NN + cb);
#pragma unroll
        for (int q = 0; q < 4; q++) wf[k][q] = p[q];
    }

    // ---- Load W_syn slice into smem (padded), zero the diagonal element
#pragma unroll
    for (int k = 0; k < RPT; k++) {
        int r = tid + k * NTHR;
        const float4* p = (const float4*)(W_syn + (size_t)r * NN + cb);
        float4* dst = (float4*)(ws + r * WS_STRIDE);
#pragma unroll
        for (int q = 0; q < 4; q++) dst[q] = p[q];
        if (r >= cb && r < cb + NC) ws[r * WS_STRIDE + (r - cb)] = 0.0f;
    }

    // ---- Per-neuron state kept in registers of threads 0..NC-1
    float v_st = 0.0f, s_st = 0.0f;
    float win0 = 0.0f, win1 = 0.0f, io = 0.0f;
    if (tid < NC) {
        int j = cb + tid;
        win0 = __ldg(W_in + j);
        win1 = __ldg(W_in + NN + j);
        io   = __ldg(I_o + j);
    }
    __syncthreads();

    for (int t = 0; t < TT; t++) {
        // ---- grid barrier: wait until every block has published step t
        if (t > 0) {
            if (tid < 32) {
                unsigned need = (unsigned)t;
                while (g_flags[lane] < need || g_flags[lane + 32] < need ||
                       g_flags[lane + 64] < need || g_flags[lane + 96] < need) { }
            }
            __syncthreads();
        }

        const float* sb  = &g_sbuf[t & 1][0];
        const float* sfb = &g_sfbuf[t & 1][0];

        // ---- load this thread's 8 s / s_fast values (bypass L1: cross-SM data)
        float sv[RPT], fv[RPT];
#pragma unroll
        for (int k = 0; k < RPT; k++) {
            int r = tid + k * NTHR;
            sv[k] = __ldcg(sb + r);
            fv[k] = __ldcg(sfb + r);
        }

        // ---- partial mat-vec: acc[c] = sum_k s*Wsyn + sfast*Wfast
        float4 a0 = make_float4(0.f,0.f,0.f,0.f);
        float4 a1 = a0, a2 = a0, a3 = a0;
#pragma unroll
        for (int k = 0; k < RPT; k++) {
            const float4* wr = (const float4*)(ws + (tid + k * NTHR) * WS_STRIDE);
            float4 w0 = wr[0], w1 = wr[1], w2 = wr[2], w3 = wr[3];
            float s = sv[k], f = fv[k];
            a0.x += s*w0.x + f*wf[k][0].x;  a0.y += s*w0.y + f*wf[k][0].y;
            a0.z += s*w0.z + f*wf[k][0].z;  a0.w += s*w0.w + f*wf[k][0].w;
            a1.x += s*w1.x + f*wf[k][1].x;  a1.y += s*w1.y + f*wf[k][1].y;
            a1.z += s*w1.z + f*wf[k][1].z;  a1.w += s*w1.w + f*wf[k][1].w;
            a2.x += s*w2.x + f*wf[k][2].x;  a2.y += s*w2.y + f*wf[k][2].y;
            a2.z += s*w2.z + f*wf[k][2].z;  a2.w += s*w2.w + f*wf[k][2].w;
            a3.x += s*w3.x + f*wf[k][3].x;  a3.y += s*w3.y + f*wf[k][3].y;
            a3.z += s*w3.z + f*wf[k][3].z;  a3.w += s*w3.w + f*wf[k][3].w;
        }

        // ---- intra-warp butterfly reduce all 16 column partials
        float v16[NC] = { a0.x,a0.y,a0.z,a0.w, a1.x,a1.y,a1.z,a1.w,
                          a2.x,a2.y,a2.z,a2.w, a3.x,a3.y,a3.z,a3.w };
#pragma unroll
        for (int c = 0; c < NC; c++) {
            float x = v16[c];
            x += __shfl_xor_sync(0xffffffffu, x, 16);
            x += __shfl_xor_sync(0xffffffffu, x, 8);
            x += __shfl_xor_sync(0xffffffffu, x, 4);
            x += __shfl_xor_sync(0xffffffffu, x, 2);
            x += __shfl_xor_sync(0xffffffffu, x, 1);
            v16[c] = x;
        }
        if (lane == 0) {
#pragma unroll
            for (int c = 0; c < NC; c++) partial[warp * NC + c] = v16[c];
        }
        __syncthreads();

        // ---- state update for the 16 owned neurons
        if (tid < NC) {
            float Irec = 0.0f;
#pragma unroll
            for (int w = 0; w < 8; w++) Irec += partial[w * NC + tid];
            float x0 = __ldg(x_in + 2 * t);
            float x1 = __ldg(x_in + 2 * t + 1);
            float Itot = Irec + x0 * win0 + x1 * win1 + io;
            float dv = __fdiv_rn(Itot - v_st, 10.0f);      // /TAU_M
            float vn = v_st + dv;
            float g   = fminf(fmaxf(vn, -1.0f), 1.0f);
            float dvc = fminf(fmaxf(dv, -1.0f), 1.0f);
            float gd  = g * dvc;
            float s_new  = s_st + __fdiv_rn(gd - s_st, 10.0f);  // /TAU_S
            float sf_new = gd;
            float sp  = (vn >= 1.0f)  ? 1.0f : 0.0f;
            float sng = (vn <= -1.0f) ? 1.0f : 0.0f;
            float v_new = (sp + 1.0f - sng) * vn;   // matches reference "not_spiked" algebra

            int j = cb + tid;
            size_t off = (size_t)t * NN + j;
            spikes_out[off] = sp;
            vs_out[off]     = v_new;
            g_shist[off]    = s_new;
            int np = (t + 1) & 1;
            __stcg(&g_sbuf[np][j],  s_new);
            __stcg(&g_sfbuf[np][j], sf_new);
            v_st = v_new; s_st = s_new;
        }

        // ---- publish: make writes GPU-visible, then raise this block's flag
        __threadfence();
        __syncthreads();
        if (tid == 0) g_flags[b] = (unsigned)(t + 1);
    }
}

// Deferred readout: readouts[t] = O @ s_hist[t]
__global__ void readout_kernel(const float* __restrict__ O, float* __restrict__ readouts) {
    int t = blockIdx.x;
    int tid = threadIdx.x;
    const float* sh = g_shist + (size_t)t * NN;
    float a0 = 0.0f, a1 = 0.0f;
    for (int j = tid; j < NN; j += blockDim.x) {
        float s = sh[j];
        a0 += O[j] * s;
        a1 += O[NN + j] * s;
    }
#pragma unroll
    for (int o = 16; o > 0; o >>= 1) {
        a0 += __shfl_xor_sync(0xffffffffu, a0, o);
        a1 += __shfl_xor_sync(0xffffffffu, a1, o);
    }
    __shared__ float r0[8], r1[8];
    if ((tid & 31) == 0) { r0[tid >> 5] = a0; r1[tid >> 5] = a1; }
    __syncthreads();
    if (tid == 0) {
        float x = 0.0f, y = 0.0f;
#pragma unroll
        for (int w = 0; w < 8; w++) { x += r0[w]; y += r1[w]; }
        readouts[2 * t]     = x;
        readouts[2 * t + 1] = y;
    }
}

extern "C" void kernel_launch(void* const* d_in, const int* in_sizes, int n_in,
                              void* d_out, int out_size) {
    const float* x_in   = (const float*)d_in[0];
    const float* W_syn  = (const float*)d_in[1];
    const float* W_fast = (const float*)d_in[2];
    const float* W_in   = (const float*)d_in[3];
    const float* I_o    = (const float*)d_in[4];
    const float* O      = (const float*)d_in[5];

    float* out      = (float*)d_out;
    float* spikes   = out;                                  // (T,N)
    float* readouts = out + (size_t)TT * NN;                // (T,2)
    float* vs       = out + (size_t)TT * NN + 2 * (size_t)TT; // (T,N)

    cudaFuncSetAttribute(nlif_kernel, cudaFuncAttributeMaxDynamicSharedMemorySize, SMEM_BYTES);

    init_kernel<<<(NN + 255) / 256, 256>>>();
    nlif_kernel<<<NBLK, NTHR, SMEM_BYTES>>>(x_in, W_syn, W_fast, W_in, I_o, spikes, vs);
    readout_kernel<<<TT, 256>>>(O, readouts);
}

// round 3
// speedup vs baseline: 1.2040x; 1.0194x over previous
#include <cuda_runtime.h>

#define NN 2048
#define TT 2048
#define NBLK 128          // persistent blocks, 1 per SM (<=148 SMs -> all co-resident)
#define NC 16             // output columns per block (128*16 = 2048)
#define NTHR 256
#define RPT 8             // rows per thread (2048/256)
#define WS_STRIDE 20      // padded floats per smem row (conflict-free LDS.128)

#define SMEM_FLOATS (NN * WS_STRIDE + 8 * NC)
#define SMEM_BYTES  (SMEM_FLOATS * 4)

// Scratch (device globals: no allocation allowed)
__device__ float g_sbuf[2][NN];
__device__ float g_sfbuf[2][NN];
__device__ float g_shist[(size_t)TT * NN];   // s_new history for deferred readout
__device__ volatile unsigned g_flags[NBLK];  // per-block epoch flags (grid barrier)

__global__ void init_kernel() {
    int i = blockIdx.x * blockDim.x + threadIdx.x;
    if (i < NN) { g_sbuf[0][i] = 0.0f; g_sfbuf[0][i] = 0.0f; }
    if (i < NBLK) g_flags[i] = 0u;
}

__global__ void __launch_bounds__(NTHR, 1) nlif_kernel(
    const float* __restrict__ x_in,   // (T,2)
    const float* __restrict__ W_syn,  // (N,N)
    const float* __restrict__ W_fast, // (N,N)
    const float* __restrict__ W_in,   // (2,N)
    const float* __restrict__ I_o,    // (N,)
    float* __restrict__ spikes_out,   // (T,N)
    float* __restrict__ vs_out)       // (T,N)
{
    extern __shared__ float sm[];
    float* ws      = sm;                    // [NN * WS_STRIDE] W_syn col slice
    float* partial = sm + NN * WS_STRIDE;   // [8 warps][NC]

    const int tid  = threadIdx.x;
    const int b    = blockIdx.x;
    const int cb   = b * NC;                // first global column owned
    const int lane = tid & 31;
    const int warp = tid >> 5;

    // ---- Load W_fast slice into registers: wf[k][q] = W_fast[tid+256k][cb+4q..+3]
    float4 wf[RPT][4];
#pragma unroll
    for (int k = 0; k < RPT; k++) {
        int r = tid + k * NTHR;
        const float4* p = (const float4*)(W_fast + (size_t)r * NN + cb);
#pragma unroll
        for (int q = 0; q < 4; q++) wf[k][q] = p[q];
    }

    // ---- Load W_syn slice into smem (padded), zero the diagonal element
#pragma unroll
    for (int k = 0; k < RPT; k++) {
        int r = tid + k * NTHR;
        const float4* p = (const float4*)(W_syn + (size_t)r * NN + cb);
        float4* dst = (float4*)(ws + r * WS_STRIDE);
#pragma unroll
        for (int q = 0; q < 4; q++) dst[q] = p[q];
        if (r >= cb && r < cb + NC) ws[r * WS_STRIDE + (r - cb)] = 0.0f;
    }

    // ---- Per-neuron state kept in registers of threads 0..NC-1
    float v_st = 0.0f, s_st = 0.0f;
    float win0 = 0.0f, win1 = 0.0f, io = 0.0f;
    if (tid < NC) {
        int j = cb + tid;
        win0 = __ldg(W_in + j);
        win1 = __ldg(W_in + NN + j);
        io   = __ldg(I_o + j);
    }
    __syncthreads();

    for (int t = 0; t < TT; t++) {
        // ---- grid barrier: wait until every block has published step t
        if (t > 0) {
            if (tid < 32) {
                unsigned need = (unsigned)t;
                while (g_flags[lane] < need || g_flags[lane + 32] < need ||
                       g_flags[lane + 64] < need || g_flags[lane + 96] < need) { }
            }
            __syncthreads();
        }

        const float* sb  = &g_sbuf[t & 1][0];
        const float* sfb = &g_sfbuf[t & 1][0];

        // ---- load this thread's 8 s / s_fast values (bypass L1: cross-SM data)
        float sv[RPT], fv[RPT];
#pragma unroll
        for (int k = 0; k < RPT; k++) {
            int r = tid + k * NTHR;
            sv[k] = __ldcg(sb + r);
            fv[k] = __ldcg(sfb + r);
        }

        // ---- partial mat-vec: acc[c] = sum_k s*Wsyn + sfast*Wfast
        float4 a0 = make_float4(0.f,0.f,0.f,0.f);
        float4 a1 = a0, a2 = a0, a3 = a0;
#pragma unroll
        for (int k = 0; k < RPT; k++) {
            const float4* wr = (const float4*)(ws + (tid + k * NTHR) * WS_STRIDE);
            float4 w0 = wr[0], w1 = wr[1], w2 = wr[2], w3 = wr[3];
            float s = sv[k], f = fv[k];
            a0.x += s*w0.x + f*wf[k][0].x;  a0.y += s*w0.y + f*wf[k][0].y;
            a0.z += s*w0.z + f*wf[k][0].z;  a0.w += s*w0.w + f*wf[k][0].w;
            a1.x += s*w1.x + f*wf[k][1].x;  a1.y += s*w1.y + f*wf[k][1].y;
            a1.z += s*w1.z + f*wf[k][1].z;  a1.w += s*w1.w + f*wf[k][1].w;
            a2.x += s*w2.x + f*wf[k][2].x;  a2.y += s*w2.y + f*wf[k][2].y;
            a2.z += s*w2.z + f*wf[k][2].z;  a2.w += s*w2.w + f*wf[k][2].w;
            a3.x += s*w3.x + f*wf[k][3].x;  a3.y += s*w3.y + f*wf[k][3].y;
            a3.z += s*w3.z + f*wf[k][3].z;  a3.w += s*w3.w + f*wf[k][3].w;
        }

        // ---- intra-warp butterfly reduce all 16 column partials
        float v16[NC] = { a0.x,a0.y,a0.z,a0.w, a1.x,a1.y,a1.z,a1.w,
                          a2.x,a2.y,a2.z,a2.w, a3.x,a3.y,a3.z,a3.w };
#pragma unroll
        for (int c = 0; c < NC; c++) {
            float x = v16[c];
            x += __shfl_xor_sync(0xffffffffu, x, 16);
            x += __shfl_xor_sync(0xffffffffu, x, 8);
            x += __shfl_xor_sync(0xffffffffu, x, 4);
            x += __shfl_xor_sync(0xffffffffu, x, 2);
            x += __shfl_xor_sync(0xffffffffu, x, 1);
            v16[c] = x;
        }
        if (lane == 0) {
#pragma unroll
            for (int c = 0; c < NC; c++) partial[warp * NC + c] = v16[c];
        }
        __syncthreads();

        // ---- state update for the 16 owned neurons
        if (tid < NC) {
            float Irec = 0.0f;
#pragma unroll
            for (int w = 0; w < 8; w++) Irec += partial[w * NC + tid];
            float x0 = __ldg(x_in + 2 * t);
            float x1 = __ldg(x_in + 2 * t + 1);
            float Itot = Irec + x0 * win0 + x1 * win1 + io;
            float dv = __fdiv_rn(Itot - v_st, 10.0f);      // /TAU_M
            float vn = v_st + dv;
            float g   = fminf(fmaxf(vn, -1.0f), 1.0f);
            float dvc = fminf(fmaxf(dv, -1.0f), 1.0f);
            float gd  = g * dvc;
            float s_new  = s_st + __fdiv_rn(gd - s_st, 10.0f);  // /TAU_S
            float sf_new = gd;
            float sp  = (vn >= 1.0f)  ? 1.0f : 0.0f;
            float sng = (vn <= -1.0f) ? 1.0f : 0.0f;
            float v_new = (sp + 1.0f - sng) * vn;   // matches reference "not_spiked" algebra

            int j = cb + tid;
            size_t off = (size_t)t * NN + j;
            spikes_out[off] = sp;
            vs_out[off]     = v_new;
            g_shist[off]    = s_new;
            int np = (t + 1) & 1;
            __stcg(&g_sbuf[np][j],  s_new);
            __stcg(&g_sfbuf[np][j], sf_new);
            v_st = v_new; s_st = s_new;
        }

        // ---- publish: make writes GPU-visible, then raise this block's flag
        __threadfence();
        __syncthreads();
        if (tid == 0) g_flags[b] = (unsigned)(t + 1);
    }
}

// Deferred readout: readouts[t] = O @ s_hist[t]
__global__ void readout_kernel(const float* __restrict__ O, float* __restrict__ readouts) {
    int t = blockIdx.x;
    int tid = threadIdx.x;
    const float* sh = g_shist + (size_t)t * NN;
    float a0 = 0.0f, a1 = 0.0f;
    for (int j = tid; j < NN; j += blockDim.x) {
        float s = sh[j];
        a0 += O[j] * s;
        a1 += O[NN + j] * s;
    }
#pragma unroll
    for (int o = 16; o > 0; o >>= 1) {
        a0 += __shfl_xor_sync(0xffffffffu, a0, o);
        a1 += __shfl_xor_sync(0xffffffffu, a1, o);
    }
    __shared__ float r0[8], r1[8];
    if ((tid & 31) == 0) { r0[tid >> 5] = a0; r1[tid >> 5] = a1; }
    __syncthreads();
    if (tid == 0) {
        float x = 0.0f, y = 0.0f;
#pragma unroll
        for (int w = 0; w < 8; w++) { x += r0[w]; y += r1[w]; }
        readouts[2 * t]     = x;
        readouts[2 * t + 1] = y;
    }
}

extern "C" void kernel_launch(void* const* d_in, const int* in_sizes, int n_in,
                              void* d_out, int out_size) {
    const float* x_in   = (const float*)d_in[0];
    const float* W_syn  = (const float*)d_in[1];
    const float* W_fast = (const float*)d_in[2];
    const float* W_in   = (const float*)d_in[3];
    const float* I_o    = (const float*)d_in[4];
    const float* O      = (const float*)d_in[5];

    float* out      = (float*)d_out;
    float* spikes   = out;                                  // (T,N)
    float* readouts = out + (size_t)TT * NN;                // (T,2)
    float* vs       = out + (size_t)TT * NN + 2 * (size_t)TT; // (T,N)

    cudaFuncSetAttribute(nlif_kernel, cudaFuncAttributeMaxDynamicSharedMemorySize, SMEM_BYTES);

    init_kernel<<<(NN + 255) / 256, 256>>>();
    nlif_kernel<<<NBLK, NTHR, SMEM_BYTES>>>(x_in, W_syn, W_fast, W_in, I_o, spikes, vs);
    readout_kernel<<<TT, 256>>>(O, readouts);
}